// round 13
// baseline (speedup 1.0000x reference)
#include <cuda_runtime.h>
#include <cuda_fp16.h>
#include <cstdint>

#define NUM_EMBED 8192
#define ED 64
#define NTOK 32768
#define CH_STRIDE 4096
#define B_STRIDE 262144

#define OFF_LOSS 2097152
#define OFF_IDX  2097153
#define OFF_BIN  (2097153 + 32768)

#define MCTA 32                      /* tokens per CTA */
#define NBLK (NTOK / MCTA)           /* 1024 */
#define KB 128                       /* codes per tile */
#define NTILES 64                    /* total code tiles */
#define NTH 38                       /* fp16-swept tiles: codes [0, 4864) */
#define NTI 26                       /* int8-swept tiles: codes [4864, 8192) */
#define CAP 96                       /* candidate slots per token */
#define WWIN 0.070f                  /* rigorous fp16-dot window */

__device__ float g_cnorm[NUM_EMBED * ED];                 // [k][c] normalized codebook fp32
__device__ __align__(16) uint32_t g_Wh[32 * NUM_EMBED];   // [c2][k] half2 channel-pairs
__device__ __align__(16) uint32_t g_Wq8[16 * NUM_EMBED];  // [cg][k] packed int8 codes
__device__ int g_ebmax_i;                                 // max per-code int error bound
__device__ float g_partial[NBLK];

// ===================== PTX helpers =====================
__device__ __forceinline__ uint32_t smem_u32(const void* p) {
    uint32_t a;
    asm("{ .reg .u64 t; cvta.to.shared.u64 t, %1; cvt.u32.u64 %0, t; }" : "=r"(a) : "l"(p));
    return a;
}
#define CP_ASYNC16(dst, src) asm volatile("cp.async.cg.shared.global [%0], [%1], 16;" :: "r"(dst), "l"(src))
#define CP_COMMIT()          asm volatile("cp.async.commit_group;" ::: "memory")
#define CP_WAIT0()           asm volatile("cp.async.wait_group 0;" ::: "memory")

__device__ __forceinline__ __half2 u2h(uint32_t u) {
    __half2 h; *reinterpret_cast<uint32_t*>(&h) = u; return h;
}
__device__ __forceinline__ int dp4a_(int a, int b, int c) {
    int d;
    asm("dp4a.s32.s32 %0, %1, %2, %3;" : "=r"(d) : "r"(a), "r"(b), "r"(c));
    return d;
}
__device__ __forceinline__ int redux_max_i(int v) {
    int d;
    asm("redux.sync.max.s32 %0, %1, 0xffffffff;" : "=r"(d) : "r"(v));
    return d;
}
// exact warp-wide float max via monotone u32 map + single redux instruction
__device__ __forceinline__ float warp_max_f(float x) {
    uint32_t u = __float_as_uint(x);
    u = (u & 0x80000000u) ? ~u : (u | 0x80000000u);
    uint32_t m;
    asm("redux.sync.max.u32 %0, %1, 0xffffffff;" : "=r"(m) : "r"(u));
    return __uint_as_float((m & 0x80000000u) ? (m & 0x7fffffffu) : ~m);
}

// quantize one normalized 64-vector; returns int error bound (127^2 units)
__device__ __forceinline__ int pack_row_err(const float* x, uint32_t* w) {
    float es = 0.f;
#pragma unroll
    for (int j = 0; j < 16; ++j) {
        int q[4];
#pragma unroll
        for (int u = 0; u < 4; ++u) {
            float xv = x[4 * j + u];
            q[u] = __float2int_rn(127.f * xv);
            float e = xv - (float)q[u] * (1.f / 127.f);
            es = fmaf(e, e, es);
        }
        w[j] = (q[0] & 0xFF) | ((q[1] & 0xFF) << 8) | ((q[2] & 0xFF) << 16) | ((q[3] & 0xFF) << 24);
    }
    float en = __fsqrt_rn(es) * 1.02f + 1e-4f;
    return (int)(16129.f * en) + 16;
}

__global__ void k0_init() { g_ebmax_i = 0; }

// ===================== prep: normalize + fp16 pair pack + int8 pack =====================
__global__ void k_prep_c(const float* __restrict__ ew) {
    int k = blockIdx.x * 128 + threadIdx.x;
    float v[64]; float ss = 0.f;
#pragma unroll
    for (int i = 0; i < 16; ++i) {
        float4 q = ((const float4*)(ew + (size_t)k * ED))[i];
        v[4*i+0] = q.x; v[4*i+1] = q.y; v[4*i+2] = q.z; v[4*i+3] = q.w;
        ss = fmaf(q.x, q.x, ss); ss = fmaf(q.y, q.y, ss);
        ss = fmaf(q.z, q.z, ss); ss = fmaf(q.w, q.w, ss);
    }
    float nm = fmaxf(__fsqrt_rn(ss), 1e-12f);
    float xn[64];
#pragma unroll
    for (int c = 0; c < 64; ++c) {
        xn[c] = __fdiv_rn(v[c], nm);
        g_cnorm[(size_t)k * ED + c] = xn[c];
    }
#pragma unroll
    for (int c2 = 0; c2 < 32; ++c2) {
        __half2 h = __floats2half2_rn(xn[2*c2], xn[2*c2+1]);
        g_Wh[c2 * NUM_EMBED + k] = *reinterpret_cast<uint32_t*>(&h);
    }
    uint32_t w[16];
    int eb = pack_row_err(xn, w);
    atomicMax(&g_ebmax_i, eb);
#pragma unroll
    for (int cg = 0; cg < 16; ++cg) g_Wq8[cg * NUM_EMBED + k] = w[cg];
}

// ===================== megakernel =====================
// CTA: 32 tokens, 128 threads; warp owns 8 tokens, lane owns 4 codes per tile.
#define SM_WH0  0                     /* 16384 */
#define SM_WH1  16384                 /* 16384 */
#define SM_WQ0  32768                 /* 8192 */
#define SM_WQ1  40960                 /* 8192 */
#define SM_ZH   49152                 /* 32*32*4 = 4096 half2 z [c2][t] */
#define SM_ZQ   53248                 /* 16*32*4 = 2048 int8 z [cg][t] */
#define SM_ZRAW 55296                 /* 64*32*4 = 8192 raw z [c][t] */
#define SM_ZS   63488                 /* 32*68*4 = 8704 normalized z [t][68] */
#define SM_NM   72192                 /* 32*4 */
#define SM_WT   72320                 /* 32*4 int window per token */
#define SM_CNT  72448                 /* 32*4 */
#define SM_IDX  72576                 /* 32*4 */
#define SM_CAND 72704                 /* 32*96*2 = 6144 */
#define SM_RED  78848                 /* 128*4 */
#define SM_BV   79360                 /* 128*4 */
#define SM_BI   79872                 /* 128*4 */
#define SM_TOT  80384

__global__ __launch_bounds__(128, 2) void k_main(const float* __restrict__ z,
                                                 const float* __restrict__ ew,
                                                 float* __restrict__ out_zq,
                                                 float* __restrict__ out_idx,
                                                 float* __restrict__ out_bin) {
    extern __shared__ char sm_[];
    uint32_t sbase = smem_u32(sm_);
    uint32_t* zh   = (uint32_t*)(sm_ + SM_ZH);
    uint32_t* zq8  = (uint32_t*)(sm_ + SM_ZQ);
    float*    zraw = (float*)(sm_ + SM_ZRAW);
    float*    zs   = (float*)(sm_ + SM_ZS);
    float*    nm   = (float*)(sm_ + SM_NM);
    int*      Wt   = (int*)(sm_ + SM_WT);
    int*      cnt  = (int*)(sm_ + SM_CNT);
    int*      idxs = (int*)(sm_ + SM_IDX);
    unsigned short* cand = (unsigned short*)(sm_ + SM_CAND);
    float*    red  = (float*)(sm_ + SM_RED);
    float*    bvr  = (float*)(sm_ + SM_BV);
    int*      bir  = (int*)(sm_ + SM_BI);

    const int tid  = threadIdx.x;
    const int warp = tid >> 5;
    const int lane = tid & 31;

    const int tok0 = blockIdx.x * MCTA;
    const int b    = tok0 >> 12;
    const int p0   = tok0 & 4095;
    const float* zb = z + (size_t)b * B_STRIDE + p0;

    // prefetch fp16 tile 0 + int8 tile 0 (= code tile NTH)
    for (int i = tid; i < 32 * 32; i += 128) {
        int c2 = i >> 5, q = i & 31;
        CP_ASYNC16(sbase + SM_WH0 + (c2 * KB + q * 4) * 4,
                   (const char*)(g_Wh + (size_t)c2 * NUM_EMBED) + q * 16);
    }
    for (int i = tid; i < 16 * 32; i += 128) {
        int cg = i >> 5, q = i & 31;
        CP_ASYNC16(sbase + SM_WQ0 + (cg * KB + q * 4) * 4,
                   (const char*)(g_Wq8 + (size_t)cg * NUM_EMBED + (size_t)NTH * KB) + q * 16);
    }
    CP_COMMIT();

    if (tid < MCTA) cnt[tid] = 0;

    // load raw z tile [c][32]
    for (int i = tid; i < 512; i += 128) {
        int c = i >> 3, q = i & 7;
        float4 v = ((const float4*)(zb + c * CH_STRIDE))[q];
        ((float4*)(zraw + c * 32))[q] = v;
    }
    __syncthreads();

    // per-token norms (identical op order to R1/R4/R11)
    if (tid < MCTA) {
        float ss = 0.f;
        for (int c = 0; c < 64; ++c) {
            float x = zraw[c * 32 + tid];
            ss = fmaf(x, x, ss);
        }
        nm[tid] = fmaxf(__fsqrt_rn(ss), 1e-12f);
    }
    __syncthreads();

    // normalized z [t][68]
    for (int i = tid; i < 64 * 32; i += 128) {
        int t = i & 31, c = i >> 5;
        zs[t * 68 + c] = __fdiv_rn(zraw[c * 32 + t], nm[t]);
    }
    __syncthreads();

    // fp16 channel-pair pack + int8 pack + int window, per token
    if (tid < MCTA) {
        const float* za = zs + tid * 68;
#pragma unroll
        for (int c2 = 0; c2 < 32; ++c2) {
            __half2 h = __floats2half2_rn(za[2*c2], za[2*c2+1]);
            zh[c2 * 32 + tid] = *reinterpret_cast<uint32_t*>(&h);
        }
        uint32_t w[16];
        int ea = pack_row_err(za, w);
#pragma unroll
        for (int cg = 0; cg < 16; ++cg) zq8[cg * 32 + tid] = w[cg];
        Wt[tid] = 2 * (ea + g_ebmax_i) + 64;
    }
    __syncthreads();

    const int t0 = warp * 8;
    const int kc0 = lane * 4;

    int wtr[8];
    float rmf[8];
    int   rmi[8];
#pragma unroll
    for (int t = 0; t < 8; ++t) {
        wtr[t] = Wt[t0 + t];
        rmf[t] = -1e30f;
        rmi[t] = -1073741824;
    }

    // ---------------- hybrid HFMA2 + dp4a sweep ----------------
    for (int it = 0; it < NTH; ++it) {
        CP_WAIT0();
        __syncthreads();

        const uint32_t* wqh = (it & 1) ? (uint32_t*)(sm_ + SM_WH1) : (uint32_t*)(sm_ + SM_WH0);
        const uint32_t* wqi = (it & 1) ? (uint32_t*)(sm_ + SM_WQ1) : (uint32_t*)(sm_ + SM_WQ0);
        const bool do_i = (it < NTI);

        // prefetch next tiles into the other buffers
        if (it + 1 < NTH) {
            uint32_t whN = (it & 1) ? (sbase + SM_WH0) : (sbase + SM_WH1);
            const char* srcH = (const char*)(g_Wh + (size_t)(it + 1) * KB);
            for (int i = tid; i < 32 * 32; i += 128) {
                int c2 = i >> 5, q = i & 31;
                CP_ASYNC16(whN + (c2 * KB + q * 4) * 4,
                           srcH + (size_t)c2 * NUM_EMBED * 4 + q * 16);
            }
            if (it + 1 < NTI) {
                uint32_t wqN = (it & 1) ? (sbase + SM_WQ0) : (sbase + SM_WQ1);
                const char* srcI = (const char*)(g_Wq8 + (size_t)(NTH + it + 1) * KB);
                for (int i = tid; i < 16 * 32; i += 128) {
                    int cg = i >> 5, q = i & 31;
                    CP_ASYNC16(wqN + (cg * KB + q * 4) * 4,
                               srcI + (size_t)cg * NUM_EMBED * 4 + q * 16);
                }
            }
            CP_COMMIT();
        }

        __half2 acc_h[8][4];
        int     acc_i[8][4];
#pragma unroll
        for (int t = 0; t < 8; ++t)
#pragma unroll
            for (int c = 0; c < 4; ++c) {
                acc_h[t][c] = __floats2half2_rn(0.f, 0.f);
                acc_i[t][c] = 0;
            }

#pragma unroll 4
        for (int u = 0; u < 32; ++u) {
            // fp16 block: channel-pair u
            {
                const uint32_t* zp = zh + u * 32 + t0;
                uint4 a0 = *(const uint4*)(zp + 0);
                uint4 a1 = *(const uint4*)(zp + 4);
                uint4 wb = *(const uint4*)(wqh + u * KB + kc0);
                __half2 av[8] = {u2h(a0.x), u2h(a0.y), u2h(a0.z), u2h(a0.w),
                                 u2h(a1.x), u2h(a1.y), u2h(a1.z), u2h(a1.w)};
                __half2 bv[4] = {u2h(wb.x), u2h(wb.y), u2h(wb.z), u2h(wb.w)};
#pragma unroll
                for (int t = 0; t < 8; ++t)
#pragma unroll
                    for (int c = 0; c < 4; ++c)
                        acc_h[t][c] = __hfma2(av[t], bv[c], acc_h[t][c]);
            }
            // int8 block: channel-group u/2 (every other u)
            if (do_i && (u & 1) == 0) {
                int cg = u >> 1;
                const uint32_t* zp = zq8 + cg * 32 + t0;
                uint4 a0 = *(const uint4*)(zp + 0);
                uint4 a1 = *(const uint4*)(zp + 4);
                uint4 wb = *(const uint4*)(wqi + cg * KB + kc0);
                uint32_t aa[8] = {a0.x, a0.y, a0.z, a0.w, a1.x, a1.y, a1.z, a1.w};
                uint32_t bb[4] = {wb.x, wb.y, wb.z, wb.w};
#pragma unroll
                for (int t = 0; t < 8; ++t)
#pragma unroll
                    for (int c = 0; c < 4; ++c)
                        acc_i[t][c] = dp4a_((int)aa[t], (int)bb[c], acc_i[t][c]);
            }
        }

        // fp16 push (codes it*KB ..)
        int kbF = it * KB + kc0;
#pragma unroll
        for (int t = 0; t < 8; ++t) {
            __half2 s0 = __hadd2(acc_h[t][0], __lowhigh2highlow(acc_h[t][0]));
            __half2 s1 = __hadd2(acc_h[t][1], __lowhigh2highlow(acc_h[t][1]));
            __half2 s2 = __hadd2(acc_h[t][2], __lowhigh2highlow(acc_h[t][2]));
            __half2 s3 = __hadd2(acc_h[t][3], __lowhigh2highlow(acc_h[t][3]));
            __half2 m2 = __hmax2(__hmax2(s0, s1), __hmax2(s2, s3));
            float flm = __low2float(m2);
            float wm = warp_max_f(flm);
            rmf[t] = fmaxf(rmf[t], wm);
            float thr = rmf[t] - WWIN;
            if (flm >= thr) {
                float d0 = __low2float(s0), d1 = __low2float(s1);
                float d2 = __low2float(s2), d3 = __low2float(s3);
                if (d0 >= thr) {
                    int pos = atomicAdd(&cnt[t0 + t], 1);
                    if (pos < CAP) cand[(t0 + t) * CAP + pos] = (unsigned short)(kbF + 0);
                }
                if (d1 >= thr) {
                    int pos = atomicAdd(&cnt[t0 + t], 1);
                    if (pos < CAP) cand[(t0 + t) * CAP + pos] = (unsigned short)(kbF + 1);
                }
                if (d2 >= thr) {
                    int pos = atomicAdd(&cnt[t0 + t], 1);
                    if (pos < CAP) cand[(t0 + t) * CAP + pos] = (unsigned short)(kbF + 2);
                }
                if (d3 >= thr) {
                    int pos = atomicAdd(&cnt[t0 + t], 1);
                    if (pos < CAP) cand[(t0 + t) * CAP + pos] = (unsigned short)(kbF + 3);
                }
            }
        }

        // int8 push (codes (NTH+it)*KB ..)
        if (do_i) {
            int kbI = (NTH + it) * KB + kc0;
#pragma unroll
            for (int t = 0; t < 8; ++t) {
                int m = max(max(acc_i[t][0], acc_i[t][1]), max(acc_i[t][2], acc_i[t][3]));
                int wm = redux_max_i(m);
                rmi[t] = max(rmi[t], wm);
                int thr = rmi[t] - wtr[t];
                if (m >= thr) {
#pragma unroll
                    for (int c = 0; c < 4; ++c) {
                        if (acc_i[t][c] >= thr) {
                            int pos = atomicAdd(&cnt[t0 + t], 1);
                            if (pos < CAP) cand[(t0 + t) * CAP + pos] = (unsigned short)(kbI + c);
                        }
                    }
                }
            }
        }
    }
    __syncthreads();

    // ---------------- exact fp32 resolve (4 threads per token) ----------------
    {
        int tk = tid >> 2, q = tid & 3;
        int n = cnt[tk];
        float bv = -1e30f; int bi = 0x7FFFFFFF;
        if (n <= CAP) {
            const float* za = zs + tk * 68;
            for (int j = q; j < n; j += 4) {
                int k = cand[tk * CAP + j];
                const float4* cr4 = (const float4*)(g_cnorm + (size_t)k * ED);
                float d = 0.f;
#pragma unroll
                for (int m = 0; m < 16; ++m) {
                    float4 u = cr4[m];
                    d = fmaf(za[4*m+0], u.x, d);
                    d = fmaf(za[4*m+1], u.y, d);
                    d = fmaf(za[4*m+2], u.z, d);
                    d = fmaf(za[4*m+3], u.w, d);
                }
                if (d > bv || (d == bv && k < bi)) { bv = d; bi = k; }
            }
        }
#pragma unroll
        for (int off = 1; off <= 2; off <<= 1) {
            float ov = __shfl_xor_sync(0xffffffffu, bv, off);
            int   oi = __shfl_xor_sync(0xffffffffu, bi, off);
            if (ov > bv || (ov == bv && oi < bi)) { bv = ov; bi = oi; }
        }
        if (q == 0) idxs[tk] = bi;
    }
    __syncthreads();

    // overflow backstop: full exact scan (rigor guarantee; ~never triggers)
    for (int tk = 0; tk < MCTA; ++tk) {
        if (cnt[tk] > CAP) {
            const float* za = zs + tk * 68;
            float bv = -1e30f; int bi = 0x7FFFFFFF;
            for (int k = tid; k < NUM_EMBED; k += 128) {
                const float4* cr4 = (const float4*)(g_cnorm + (size_t)k * ED);
                float d = 0.f;
#pragma unroll
                for (int m = 0; m < 16; ++m) {
                    float4 u = cr4[m];
                    d = fmaf(za[4*m+0], u.x, d);
                    d = fmaf(za[4*m+1], u.y, d);
                    d = fmaf(za[4*m+2], u.z, d);
                    d = fmaf(za[4*m+3], u.w, d);
                }
                if (d > bv || (d == bv && k < bi)) { bv = d; bi = k; }
            }
            bvr[tid] = bv; bir[tid] = bi;
            __syncthreads();
            for (int s = 64; s > 0; s >>= 1) {
                if (tid < s) {
                    float v2 = bvr[tid + s]; int i2 = bir[tid + s];
                    if (v2 > bvr[tid] || (v2 == bvr[tid] && i2 < bir[tid])) {
                        bvr[tid] = v2; bir[tid] = i2;
                    }
                }
                __syncthreads();
            }
            if (tid == 0) idxs[tk] = bir[0];
            __syncthreads();
        }
    }
    __syncthreads();

    // ---------------- fused epilogue: gather/STE/loss/idx/bin ----------------
    int myidx = idxs[lane];
    const float4* er = (const float4*)(ew + (size_t)myidx * ED + warp * 16);
    float4 e0 = er[0], e1 = er[1], e2 = er[2], e3 = er[3];
    float vals[16] = {e0.x, e0.y, e0.z, e0.w, e1.x, e1.y, e1.z, e1.w,
                      e2.x, e2.y, e2.z, e2.w, e3.x, e3.y, e3.z, e3.w};
    float ssq = 0.f;
#pragma unroll
    for (int j = 0; j < 16; ++j) {
        int ch = warp * 16 + j;
        float zc = zraw[ch * 32 + lane];
        float d  = vals[j] - zc;
        out_zq[(size_t)(b * 64 + ch) * 4096 + p0 + lane] = zc + d;
        ssq = fmaf(d, d, ssq);
    }
    red[tid] = ssq;
    __syncthreads();
    for (int s = 64; s > 0; s >>= 1) {
        if (tid < s) red[tid] += red[tid + s];
        __syncthreads();
    }
    if (tid == 0) g_partial[blockIdx.x] = red[0];

    if (tid < MCTA) {
        out_idx[tok0 + tid] = (float)idxs[tid];
        atomicAdd(&out_bin[idxs[tid]], 1.0f);
    }
}

// ---------------- loss finalize ----------------
__global__ void k4_loss(float* __restrict__ out_loss) {
    int lane = threadIdx.x;
    float s = 0.f;
    for (int i = lane * 32; i < lane * 32 + 32; ++i) s += g_partial[i];
#pragma unroll
    for (int off = 16; off > 0; off >>= 1)
        s += __shfl_xor_sync(0xffffffffu, s, off);
    if (lane == 0) {
        float m = s / 2097152.0f;
        out_loss[0] = 0.25f * m + m;
    }
}

extern "C" void kernel_launch(void* const* d_in, const int* in_sizes, int n_in,
                              void* d_out, int out_size) {
    const float* z  = (const float*)d_in[0];
    const float* ew = (const float*)d_in[1];
    float* out      = (float*)d_out;

    float* out_zq   = out;
    float* out_loss = out + OFF_LOSS;
    float* out_idx  = out + OFF_IDX;
    float* out_bin  = out + OFF_BIN;

    cudaMemsetAsync(out_bin, 0, NUM_EMBED * sizeof(float));

    k0_init<<<1, 1>>>();
    k_prep_c<<<NUM_EMBED / 128, 128>>>(ew);

    cudaFuncSetAttribute(k_main, cudaFuncAttributeMaxDynamicSharedMemorySize, SM_TOT);
    k_main<<<NBLK, 128, SM_TOT>>>(z, ew, out_zq, out_idx, out_bin);

    k4_loss<<<1, 32>>>(out_loss);
}

// round 14
// speedup vs baseline: 2.1306x; 2.1306x over previous
#include <cuda_runtime.h>
#include <cuda_fp16.h>
#include <cstdint>

#define NUM_EMBED 8192
#define ED 64
#define NTOK 32768
#define CH_STRIDE 4096
#define B_STRIDE 262144

#define OFF_LOSS 2097152
#define OFF_IDX  2097153
#define OFF_BIN  (2097153 + 32768)

#define MCTA 32                      /* tokens per CTA */
#define NBLK (NTOK / MCTA)           /* 1024 */
#define KB 128                       /* codes per tile */
#define NTILES (NUM_EMBED / KB)      /* 64 */
#define CAP 96                       /* candidate slots per token */
#define WWIN 0.070f                  /* rigorous fp16-dot window */

__device__ float g_cnorm[NUM_EMBED * ED];                 // [k][c] normalized codebook fp32
__device__ __align__(16) uint32_t g_Wh[32 * NUM_EMBED];   // [c2][k] half2 channel-pairs
__device__ float g_partial[NBLK];

// ===================== PTX helpers =====================
__device__ __forceinline__ uint32_t smem_u32(const void* p) {
    uint32_t a;
    asm("{ .reg .u64 t; cvta.to.shared.u64 t, %1; cvt.u32.u64 %0, t; }" : "=r"(a) : "l"(p));
    return a;
}
#define CP_ASYNC16(dst, src) asm volatile("cp.async.cg.shared.global [%0], [%1], 16;" :: "r"(dst), "l"(src))
#define CP_COMMIT()          asm volatile("cp.async.commit_group;" ::: "memory")
#define CP_WAIT0()           asm volatile("cp.async.wait_group 0;" ::: "memory")

__device__ __forceinline__ __half2 u2h(uint32_t u) {
    __half2 h; *reinterpret_cast<uint32_t*>(&h) = u; return h;
}

// exact warp-wide float max via monotone u32 map + single redux instruction
__device__ __forceinline__ float warp_max_f(float x) {
    uint32_t u = __float_as_uint(x);
    u = (u & 0x80000000u) ? ~u : (u | 0x80000000u);
    uint32_t m;
    asm("redux.sync.max.u32 %0, %1, 0xffffffff;" : "=r"(m) : "r"(u));
    return __uint_as_float((m & 0x80000000u) ? (m & 0x7fffffffu) : ~m);
}

// ===================== prep: normalize + fp16 channel-pair pack + bin zero =====================
__global__ void k_prep_c(const float* __restrict__ ew, float* __restrict__ out_bin) {
    int k = blockIdx.x * 128 + threadIdx.x;
    out_bin[k] = 0.f;   // grid covers exactly NUM_EMBED entries
    float v[64]; float ss = 0.f;
#pragma unroll
    for (int i = 0; i < 16; ++i) {
        float4 q = ((const float4*)(ew + (size_t)k * ED))[i];
        v[4*i+0] = q.x; v[4*i+1] = q.y; v[4*i+2] = q.z; v[4*i+3] = q.w;
        ss = fmaf(q.x, q.x, ss); ss = fmaf(q.y, q.y, ss);
        ss = fmaf(q.z, q.z, ss); ss = fmaf(q.w, q.w, ss);
    }
    float nm = fmaxf(__fsqrt_rn(ss), 1e-12f);
    float xn[64];
#pragma unroll
    for (int c = 0; c < 64; ++c) {
        xn[c] = __fdiv_rn(v[c], nm);
        g_cnorm[(size_t)k * ED + c] = xn[c];
    }
#pragma unroll
    for (int c2 = 0; c2 < 32; ++c2) {
        __half2 h = __floats2half2_rn(xn[2*c2], xn[2*c2+1]);
        g_Wh[c2 * NUM_EMBED + k] = *reinterpret_cast<uint32_t*>(&h);
    }
}

// ===================== megakernel =====================
// CTA: 32 tokens, 128 threads; warp owns 8 tokens, lane owns 4 codes per KB=128 tile.
#define SM_WH0  0                     /* 32*128*4 = 16384 */
#define SM_WH1  16384                 /* 16384 */
#define SM_ZH   32768                 /* 32*32*4 = 4096 half2 z [c2][t] */
#define SM_ZRAW 36864                 /* 64*32*4 = 8192 raw z [c][t] */
#define SM_ZS   45056                 /* 32*68*4 = 8704 normalized z [t][68] */
#define SM_NM   53760                 /* 32*4 */
#define SM_CNT  53888                 /* 32*4 */
#define SM_IDX  54016                 /* 32*4 */
#define SM_CAND 54144                 /* 32*96*2 = 6144 */
#define SM_RED  60288                 /* 128*4 */
#define SM_BV   60800                 /* 128*4 */
#define SM_BI   61312                 /* 128*4 */
#define SM_TOT  61824

__global__ __launch_bounds__(128, 3) void k_main(const float* __restrict__ z,
                                                 const float* __restrict__ ew,
                                                 float* __restrict__ out_zq,
                                                 float* __restrict__ out_idx,
                                                 float* __restrict__ out_bin) {
    extern __shared__ char sm_[];
    uint32_t sbase = smem_u32(sm_);
    uint32_t* zh   = (uint32_t*)(sm_ + SM_ZH);
    float*    zraw = (float*)(sm_ + SM_ZRAW);
    float*    zs   = (float*)(sm_ + SM_ZS);
    float*    nm   = (float*)(sm_ + SM_NM);
    int*      cnt  = (int*)(sm_ + SM_CNT);
    int*      idxs = (int*)(sm_ + SM_IDX);
    unsigned short* cand = (unsigned short*)(sm_ + SM_CAND);
    float*    red  = (float*)(sm_ + SM_RED);
    float*    bvr  = (float*)(sm_ + SM_BV);
    int*      bir  = (int*)(sm_ + SM_BI);

    const int tid  = threadIdx.x;
    const int warp = tid >> 5;
    const int lane = tid & 31;

    const int tok0 = blockIdx.x * MCTA;
    const int b    = tok0 >> 12;
    const int p0   = tok0 & 4095;
    const float* zb = z + (size_t)b * B_STRIDE + p0;

    // prefetch codebook tile 0 (32 c2-rows x 512B)
    for (int i = tid; i < 32 * 32; i += 128) {
        int c2 = i >> 5, q = i & 31;
        CP_ASYNC16(sbase + SM_WH0 + (c2 * KB + q * 4) * 4,
                   (const char*)(g_Wh + (size_t)c2 * NUM_EMBED) + q * 16);
    }
    CP_COMMIT();

    if (tid < MCTA) cnt[tid] = 0;

    // load raw z tile [c][32]
    for (int i = tid; i < 512; i += 128) {
        int c = i >> 3, q = i & 7;
        float4 v = ((const float4*)(zb + c * CH_STRIDE))[q];
        ((float4*)(zraw + c * 32))[q] = v;
    }
    __syncthreads();

    // per-token norms (identical op order to R1/R4/R11)
    if (tid < MCTA) {
        float ss = 0.f;
        for (int c = 0; c < 64; ++c) {
            float x = zraw[c * 32 + tid];
            ss = fmaf(x, x, ss);
        }
        nm[tid] = fmaxf(__fsqrt_rn(ss), 1e-12f);
    }
    __syncthreads();

    // normalized z [t][68]
    for (int i = tid; i < 64 * 32; i += 128) {
        int t = i & 31, c = i >> 5;
        zs[t * 68 + c] = __fdiv_rn(zraw[c * 32 + t], nm[t]);
    }
    __syncthreads();

    // fp16 channel-pair pack of z: zh[c2][t]
    for (int i = tid; i < 32 * 32; i += 128) {
        int c2 = i >> 5, t = i & 31;
        __half2 h = __floats2half2_rn(zs[t * 68 + 2*c2], zs[t * 68 + 2*c2 + 1]);
        zh[c2 * 32 + t] = *reinterpret_cast<uint32_t*>(&h);
    }
    __syncthreads();

    const int t0 = warp * 8;
    const int kc0 = lane * 4;

    float rmf[8];
#pragma unroll
    for (int t = 0; t < 8; ++t) rmf[t] = -1e30f;

    // ---------------- HFMA2 sweep with rigorous candidate push ----------------
    for (int nt = 0; nt < NTILES; ++nt) {
        CP_WAIT0();
        __syncthreads();

        const uint32_t* wq = (nt & 1) ? (uint32_t*)(sm_ + SM_WH1) : (uint32_t*)(sm_ + SM_WH0);

        if (nt + 1 < NTILES) {
            uint32_t wsN = (nt & 1) ? (sbase + SM_WH0) : (sbase + SM_WH1);
            const char* src0 = (const char*)(g_Wh + (size_t)(nt + 1) * KB);
            for (int i = tid; i < 32 * 32; i += 128) {
                int c2 = i >> 5, q = i & 31;
                CP_ASYNC16(wsN + (c2 * KB + q * 4) * 4,
                           src0 + (size_t)c2 * NUM_EMBED * 4 + q * 16);
            }
            CP_COMMIT();
        }

        __half2 acc[8][4];
#pragma unroll
        for (int t = 0; t < 8; ++t)
#pragma unroll
            for (int c = 0; c < 4; ++c) acc[t][c] = __floats2half2_rn(0.f, 0.f);

#pragma unroll 8
        for (int c2 = 0; c2 < 32; ++c2) {
            const uint32_t* zp = zh + c2 * 32 + t0;
            uint4 a0 = *(const uint4*)(zp + 0);
            uint4 a1 = *(const uint4*)(zp + 4);
            uint4 wb = *(const uint4*)(wq + c2 * KB + kc0);
            __half2 av[8] = {u2h(a0.x), u2h(a0.y), u2h(a0.z), u2h(a0.w),
                             u2h(a1.x), u2h(a1.y), u2h(a1.z), u2h(a1.w)};
            __half2 bv[4] = {u2h(wb.x), u2h(wb.y), u2h(wb.z), u2h(wb.w)};
#pragma unroll
            for (int t = 0; t < 8; ++t)
#pragma unroll
                for (int c = 0; c < 4; ++c)
                    acc[t][c] = __hfma2(av[t], bv[c], acc[t][c]);
        }

        // per-token tile max + window push
        int kbase = nt * KB + kc0;
#pragma unroll
        for (int t = 0; t < 8; ++t) {
            __half2 s0 = __hadd2(acc[t][0], __lowhigh2highlow(acc[t][0]));
            __half2 s1 = __hadd2(acc[t][1], __lowhigh2highlow(acc[t][1]));
            __half2 s2 = __hadd2(acc[t][2], __lowhigh2highlow(acc[t][2]));
            __half2 s3 = __hadd2(acc[t][3], __lowhigh2highlow(acc[t][3]));
            __half2 m2 = __hmax2(__hmax2(s0, s1), __hmax2(s2, s3));
            float flm = __low2float(m2);
            float wm = warp_max_f(flm);
            rmf[t] = fmaxf(rmf[t], wm);
            float thr = rmf[t] - WWIN;
            if (flm >= thr) {   // early-out: this lane holds a candidate (rare)
                float d0 = __low2float(s0), d1 = __low2float(s1);
                float d2 = __low2float(s2), d3 = __low2float(s3);
                if (d0 >= thr) {
                    int pos = atomicAdd(&cnt[t0 + t], 1);
                    if (pos < CAP) cand[(t0 + t) * CAP + pos] = (unsigned short)(kbase + 0);
                }
                if (d1 >= thr) {
                    int pos = atomicAdd(&cnt[t0 + t], 1);
                    if (pos < CAP) cand[(t0 + t) * CAP + pos] = (unsigned short)(kbase + 1);
                }
                if (d2 >= thr) {
                    int pos = atomicAdd(&cnt[t0 + t], 1);
                    if (pos < CAP) cand[(t0 + t) * CAP + pos] = (unsigned short)(kbase + 2);
                }
                if (d3 >= thr) {
                    int pos = atomicAdd(&cnt[t0 + t], 1);
                    if (pos < CAP) cand[(t0 + t) * CAP + pos] = (unsigned short)(kbase + 3);
                }
            }
        }
    }
    __syncthreads();

    // ---------------- exact fp32 resolve (4 threads per token) ----------------
    {
        int tk = tid >> 2, q = tid & 3;
        int n = cnt[tk];
        float bv = -1e30f; int bi = 0x7FFFFFFF;
        if (n <= CAP) {
            const float* za = zs + tk * 68;
            for (int j = q; j < n; j += 4) {
                int k = cand[tk * CAP + j];
                const float4* cr4 = (const float4*)(g_cnorm + (size_t)k * ED);
                float d = 0.f;
#pragma unroll
                for (int m = 0; m < 16; ++m) {
                    float4 u = cr4[m];
                    d = fmaf(za[4*m+0], u.x, d);
                    d = fmaf(za[4*m+1], u.y, d);
                    d = fmaf(za[4*m+2], u.z, d);
                    d = fmaf(za[4*m+3], u.w, d);
                }
                if (d > bv || (d == bv && k < bi)) { bv = d; bi = k; }
            }
        }
#pragma unroll
        for (int off = 1; off <= 2; off <<= 1) {
            float ov = __shfl_xor_sync(0xffffffffu, bv, off);
            int   oi = __shfl_xor_sync(0xffffffffu, bi, off);
            if (ov > bv || (ov == bv && oi < bi)) { bv = ov; bi = oi; }
        }
        if (q == 0) idxs[tk] = bi;
    }
    __syncthreads();

    // overflow backstop: full exact scan (rigor guarantee; ~never triggers)
    for (int tk = 0; tk < MCTA; ++tk) {
        if (cnt[tk] > CAP) {
            const float* za = zs + tk * 68;
            float bv = -1e30f; int bi = 0x7FFFFFFF;
            for (int k = tid; k < NUM_EMBED; k += 128) {
                const float4* cr4 = (const float4*)(g_cnorm + (size_t)k * ED);
                float d = 0.f;
#pragma unroll
                for (int m = 0; m < 16; ++m) {
                    float4 u = cr4[m];
                    d = fmaf(za[4*m+0], u.x, d);
                    d = fmaf(za[4*m+1], u.y, d);
                    d = fmaf(za[4*m+2], u.z, d);
                    d = fmaf(za[4*m+3], u.w, d);
                }
                if (d > bv || (d == bv && k < bi)) { bv = d; bi = k; }
            }
            bvr[tid] = bv; bir[tid] = bi;
            __syncthreads();
            for (int s = 64; s > 0; s >>= 1) {
                if (tid < s) {
                    float v2 = bvr[tid + s]; int i2 = bir[tid + s];
                    if (v2 > bvr[tid] || (v2 == bvr[tid] && i2 < bir[tid])) {
                        bvr[tid] = v2; bir[tid] = i2;
                    }
                }
                __syncthreads();
            }
            if (tid == 0) idxs[tk] = bir[0];
            __syncthreads();
        }
    }
    __syncthreads();

    // ---------------- fused epilogue: gather/STE/loss/idx/bin ----------------
    int myidx = idxs[lane];
    const float4* er = (const float4*)(ew + (size_t)myidx * ED + warp * 16);
    float4 e0 = er[0], e1 = er[1], e2 = er[2], e3 = er[3];
    float vals[16] = {e0.x, e0.y, e0.z, e0.w, e1.x, e1.y, e1.z, e1.w,
                      e2.x, e2.y, e2.z, e2.w, e3.x, e3.y, e3.z, e3.w};
    float ssq = 0.f;
#pragma unroll
    for (int j = 0; j < 16; ++j) {
        int ch = warp * 16 + j;
        float zc = zraw[ch * 32 + lane];
        float d  = vals[j] - zc;
        out_zq[(size_t)(b * 64 + ch) * 4096 + p0 + lane] = zc + d;
        ssq = fmaf(d, d, ssq);
    }
    red[tid] = ssq;
    __syncthreads();
    for (int s = 64; s > 0; s >>= 1) {
        if (tid < s) red[tid] += red[tid + s];
        __syncthreads();
    }
    if (tid == 0) g_partial[blockIdx.x] = red[0];

    if (tid < MCTA) {
        out_idx[tok0 + tid] = (float)idxs[tid];
        atomicAdd(&out_bin[idxs[tid]], 1.0f);
    }
}

// ---------------- loss finalize ----------------
__global__ void k4_loss(float* __restrict__ out_loss) {
    int lane = threadIdx.x;
    float s = 0.f;
    for (int i = lane * 32; i < lane * 32 + 32; ++i) s += g_partial[i];
#pragma unroll
    for (int off = 16; off > 0; off >>= 1)
        s += __shfl_xor_sync(0xffffffffu, s, off);
    if (lane == 0) {
        float m = s / 2097152.0f;
        out_loss[0] = 0.25f * m + m;
    }
}

extern "C" void kernel_launch(void* const* d_in, const int* in_sizes, int n_in,
                              void* d_out, int out_size) {
    const float* z  = (const float*)d_in[0];
    const float* ew = (const float*)d_in[1];
    float* out      = (float*)d_out;

    float* out_zq   = out;
    float* out_loss = out + OFF_LOSS;
    float* out_idx  = out + OFF_IDX;
    float* out_bin  = out + OFF_BIN;

    k_prep_c<<<NUM_EMBED / 128, 128>>>(ew, out_bin);

    cudaFuncSetAttribute(k_main, cudaFuncAttributeMaxDynamicSharedMemorySize, SM_TOT);
    k_main<<<NBLK, 128, SM_TOT>>>(z, ew, out_zq, out_idx, out_bin);

    k4_loss<<<1, 32>>>(out_loss);
}

// round 15
// speedup vs baseline: 2.2292x; 1.0463x over previous
#include <cuda_runtime.h>
#include <cuda_fp16.h>
#include <cstdint>

#define NUM_EMBED 8192
#define ED 64
#define NTOK 32768
#define CH_STRIDE 4096
#define B_STRIDE 262144

#define OFF_LOSS 2097152
#define OFF_IDX  2097153
#define OFF_BIN  (2097153 + 32768)

#define MCTA 32                      /* tokens per CTA */
#define NBLK (NTOK / MCTA)           /* 1024 */
#define KB 128                       /* codes per tile */
#define NTILES (NUM_EMBED / KB)      /* 64 */
#define CAP 96                       /* candidate slots per token */
#define WWIN 0.070f                  /* rigorous fp16-dot window */

__device__ float g_cnorm[NUM_EMBED * ED];                 // [k][c] normalized codebook fp32
__device__ __align__(16) uint32_t g_Wh[32 * NUM_EMBED];   // [c2][k] half2 channel-pairs
__device__ float g_partial[NBLK];

// ===================== PTX helpers =====================
__device__ __forceinline__ uint32_t smem_u32(const void* p) {
    uint32_t a;
    asm("{ .reg .u64 t; cvta.to.shared.u64 t, %1; cvt.u32.u64 %0, t; }" : "=r"(a) : "l"(p));
    return a;
}
#define CP_ASYNC16(dst, src) asm volatile("cp.async.cg.shared.global [%0], [%1], 16;" :: "r"(dst), "l"(src))
#define CP_COMMIT()          asm volatile("cp.async.commit_group;" ::: "memory")
#define CP_WAIT0()           asm volatile("cp.async.wait_group 0;" ::: "memory")

__device__ __forceinline__ __half2 u2h(uint32_t u) {
    __half2 h; *reinterpret_cast<uint32_t*>(&h) = u; return h;
}

// exact warp-wide float max via monotone u32 map + single redux instruction
__device__ __forceinline__ float warp_max_f(float x) {
    uint32_t u = __float_as_uint(x);
    u = (u & 0x80000000u) ? ~u : (u | 0x80000000u);
    uint32_t m;
    asm("redux.sync.max.u32 %0, %1, 0xffffffff;" : "=r"(m) : "r"(u));
    return __uint_as_float((m & 0x80000000u) ? (m & 0x7fffffffu) : ~m);
}

// ===================== prep: normalize + fp16 channel-pair pack + bin zero =====================
__global__ void k_prep_c(const float* __restrict__ ew, float* __restrict__ out_bin) {
    int k = blockIdx.x * 128 + threadIdx.x;
    out_bin[k] = 0.f;   // grid covers exactly NUM_EMBED entries
    float v[64]; float ss = 0.f;
#pragma unroll
    for (int i = 0; i < 16; ++i) {
        float4 q = ((const float4*)(ew + (size_t)k * ED))[i];
        v[4*i+0] = q.x; v[4*i+1] = q.y; v[4*i+2] = q.z; v[4*i+3] = q.w;
        ss = fmaf(q.x, q.x, ss); ss = fmaf(q.y, q.y, ss);
        ss = fmaf(q.z, q.z, ss); ss = fmaf(q.w, q.w, ss);
    }
    float nm = fmaxf(__fsqrt_rn(ss), 1e-12f);
    float xn[64];
#pragma unroll
    for (int c = 0; c < 64; ++c) {
        xn[c] = __fdiv_rn(v[c], nm);
        g_cnorm[(size_t)k * ED + c] = xn[c];
    }
#pragma unroll
    for (int c2 = 0; c2 < 32; ++c2) {
        __half2 h = __floats2half2_rn(xn[2*c2], xn[2*c2+1]);
        g_Wh[c2 * NUM_EMBED + k] = *reinterpret_cast<uint32_t*>(&h);
    }
}

// ===================== megakernel =====================
// CTA: 32 tokens, 128 threads; warp owns 8 tokens, lane owns 4 codes per KB=128 tile.
// Raw z is STAGED in WH1 during setup (WH1 dead until first in-loop prefetch),
// epilogue re-reads raw z from global -> no persistent zraw buffer -> occ 4.
#define SM_WH0  0                     /* 32*128*4 = 16384 */
#define SM_WH1  16384                 /* 16384 (stage raw z here during setup) */
#define SM_ZH   32768                 /* 32*32*4 = 4096 half2 z [c2][t] */
#define SM_ZS   36864                 /* 32*68*4 = 8704 normalized z [t][68] */
#define SM_NM   45568                 /* 32*4 */
#define SM_CNT  45696                 /* 32*4 */
#define SM_IDX  45824                 /* 32*4 */
#define SM_CAND 45952                 /* 32*96*2 = 6144 */
#define SM_RED  52096                 /* 128*4 */
#define SM_BV   52608                 /* 128*4 */
#define SM_BI   53120                 /* 128*4 */
#define SM_TOT  53632

__global__ __launch_bounds__(128, 4) void k_main(const float* __restrict__ z,
                                                 const float* __restrict__ ew,
                                                 float* __restrict__ out_zq,
                                                 float* __restrict__ out_idx,
                                                 float* __restrict__ out_bin) {
    extern __shared__ char sm_[];
    uint32_t sbase = smem_u32(sm_);
    uint32_t* zh   = (uint32_t*)(sm_ + SM_ZH);
    float*    zstage = (float*)(sm_ + SM_WH1);    // raw z [c][t], setup only
    float*    zs   = (float*)(sm_ + SM_ZS);
    float*    nm   = (float*)(sm_ + SM_NM);
    int*      cnt  = (int*)(sm_ + SM_CNT);
    int*      idxs = (int*)(sm_ + SM_IDX);
    unsigned short* cand = (unsigned short*)(sm_ + SM_CAND);
    float*    red  = (float*)(sm_ + SM_RED);
    float*    bvr  = (float*)(sm_ + SM_BV);
    int*      bir  = (int*)(sm_ + SM_BI);

    const int tid  = threadIdx.x;
    const int warp = tid >> 5;
    const int lane = tid & 31;

    const int tok0 = blockIdx.x * MCTA;
    const int b    = tok0 >> 12;
    const int p0   = tok0 & 4095;
    const float* zb = z + (size_t)b * B_STRIDE + p0;

    // prefetch codebook tile 0 (32 c2-rows x 512B) into WH0
    for (int i = tid; i < 32 * 32; i += 128) {
        int c2 = i >> 5, q = i & 31;
        CP_ASYNC16(sbase + SM_WH0 + (c2 * KB + q * 4) * 4,
                   (const char*)(g_Wh + (size_t)c2 * NUM_EMBED) + q * 16);
    }
    CP_COMMIT();

    if (tid < MCTA) cnt[tid] = 0;

    // stage raw z tile [c][32] in WH1
    for (int i = tid; i < 512; i += 128) {
        int c = i >> 3, q = i & 7;
        float4 v = ((const float4*)(zb + c * CH_STRIDE))[q];
        ((float4*)(zstage + c * 32))[q] = v;
    }
    __syncthreads();

    // per-token norms (identical op order to R1/R4/R11/R14)
    if (tid < MCTA) {
        float ss = 0.f;
        for (int c = 0; c < 64; ++c) {
            float x = zstage[c * 32 + tid];
            ss = fmaf(x, x, ss);
        }
        nm[tid] = fmaxf(__fsqrt_rn(ss), 1e-12f);
    }
    __syncthreads();

    // normalized z [t][68]
    for (int i = tid; i < 64 * 32; i += 128) {
        int t = i & 31, c = i >> 5;
        zs[t * 68 + c] = __fdiv_rn(zstage[c * 32 + t], nm[t]);
    }
    __syncthreads();

    // fp16 channel-pair pack of z: zh[c2][t]   (zstage dead after this sync)
    for (int i = tid; i < 32 * 32; i += 128) {
        int c2 = i >> 5, t = i & 31;
        __half2 h = __floats2half2_rn(zs[t * 68 + 2*c2], zs[t * 68 + 2*c2 + 1]);
        zh[c2 * 32 + t] = *reinterpret_cast<uint32_t*>(&h);
    }
    __syncthreads();

    const int t0 = warp * 8;
    const int kc0 = lane * 4;

    float rmf[8];
#pragma unroll
    for (int t = 0; t < 8; ++t) rmf[t] = -1e30f;

    // ---------------- HFMA2 sweep with rigorous candidate push ----------------
    for (int nt = 0; nt < NTILES; ++nt) {
        CP_WAIT0();
        __syncthreads();

        const uint32_t* wq = (nt & 1) ? (uint32_t*)(sm_ + SM_WH1) : (uint32_t*)(sm_ + SM_WH0);

        if (nt + 1 < NTILES) {
            uint32_t wsN = (nt & 1) ? (sbase + SM_WH0) : (sbase + SM_WH1);
            const char* src0 = (const char*)(g_Wh + (size_t)(nt + 1) * KB);
            for (int i = tid; i < 32 * 32; i += 128) {
                int c2 = i >> 5, q = i & 31;
                CP_ASYNC16(wsN + (c2 * KB + q * 4) * 4,
                           src0 + (size_t)c2 * NUM_EMBED * 4 + q * 16);
            }
            CP_COMMIT();
        }

        __half2 acc[8][4];
#pragma unroll
        for (int t = 0; t < 8; ++t)
#pragma unroll
            for (int c = 0; c < 4; ++c) acc[t][c] = __floats2half2_rn(0.f, 0.f);

#pragma unroll 8
        for (int c2 = 0; c2 < 32; ++c2) {
            const uint32_t* zp = zh + c2 * 32 + t0;
            uint4 a0 = *(const uint4*)(zp + 0);
            uint4 a1 = *(const uint4*)(zp + 4);
            uint4 wb = *(const uint4*)(wq + c2 * KB + kc0);
            __half2 av[8] = {u2h(a0.x), u2h(a0.y), u2h(a0.z), u2h(a0.w),
                             u2h(a1.x), u2h(a1.y), u2h(a1.z), u2h(a1.w)};
            __half2 bv[4] = {u2h(wb.x), u2h(wb.y), u2h(wb.z), u2h(wb.w)};
#pragma unroll
            for (int t = 0; t < 8; ++t)
#pragma unroll
                for (int c = 0; c < 4; ++c)
                    acc[t][c] = __hfma2(av[t], bv[c], acc[t][c]);
        }

        // per-token tile max + window push
        int kbase = nt * KB + kc0;
#pragma unroll
        for (int t = 0; t < 8; ++t) {
            __half2 s0 = __hadd2(acc[t][0], __lowhigh2highlow(acc[t][0]));
            __half2 s1 = __hadd2(acc[t][1], __lowhigh2highlow(acc[t][1]));
            __half2 s2 = __hadd2(acc[t][2], __lowhigh2highlow(acc[t][2]));
            __half2 s3 = __hadd2(acc[t][3], __lowhigh2highlow(acc[t][3]));
            __half2 m2 = __hmax2(__hmax2(s0, s1), __hmax2(s2, s3));
            float flm = __low2float(m2);
            float wm = warp_max_f(flm);
            rmf[t] = fmaxf(rmf[t], wm);
            float thr = rmf[t] - WWIN;
            if (flm >= thr) {   // early-out: this lane holds a candidate (rare)
                float d0 = __low2float(s0), d1 = __low2float(s1);
                float d2 = __low2float(s2), d3 = __low2float(s3);
                if (d0 >= thr) {
                    int pos = atomicAdd(&cnt[t0 + t], 1);
                    if (pos < CAP) cand[(t0 + t) * CAP + pos] = (unsigned short)(kbase + 0);
                }
                if (d1 >= thr) {
                    int pos = atomicAdd(&cnt[t0 + t], 1);
                    if (pos < CAP) cand[(t0 + t) * CAP + pos] = (unsigned short)(kbase + 1);
                }
                if (d2 >= thr) {
                    int pos = atomicAdd(&cnt[t0 + t], 1);
                    if (pos < CAP) cand[(t0 + t) * CAP + pos] = (unsigned short)(kbase + 2);
                }
                if (d3 >= thr) {
                    int pos = atomicAdd(&cnt[t0 + t], 1);
                    if (pos < CAP) cand[(t0 + t) * CAP + pos] = (unsigned short)(kbase + 3);
                }
            }
        }
    }
    __syncthreads();

    // ---------------- exact fp32 resolve (4 threads per token) ----------------
    {
        int tk = tid >> 2, q = tid & 3;
        int n = cnt[tk];
        float bv = -1e30f; int bi = 0x7FFFFFFF;
        if (n <= CAP) {
            const float* za = zs + tk * 68;
            for (int j = q; j < n; j += 4) {
                int k = cand[tk * CAP + j];
                const float4* cr4 = (const float4*)(g_cnorm + (size_t)k * ED);
                float d = 0.f;
#pragma unroll
                for (int m = 0; m < 16; ++m) {
                    float4 u = cr4[m];
                    d = fmaf(za[4*m+0], u.x, d);
                    d = fmaf(za[4*m+1], u.y, d);
                    d = fmaf(za[4*m+2], u.z, d);
                    d = fmaf(za[4*m+3], u.w, d);
                }
                if (d > bv || (d == bv && k < bi)) { bv = d; bi = k; }
            }
        }
#pragma unroll
        for (int off = 1; off <= 2; off <<= 1) {
            float ov = __shfl_xor_sync(0xffffffffu, bv, off);
            int   oi = __shfl_xor_sync(0xffffffffu, bi, off);
            if (ov > bv || (ov == bv && oi < bi)) { bv = ov; bi = oi; }
        }
        if (q == 0) idxs[tk] = bi;
    }
    __syncthreads();

    // overflow backstop: full exact scan (rigor guarantee; ~never triggers)
    for (int tk = 0; tk < MCTA; ++tk) {
        if (cnt[tk] > CAP) {
            const float* za = zs + tk * 68;
            float bv = -1e30f; int bi = 0x7FFFFFFF;
            for (int k = tid; k < NUM_EMBED; k += 128) {
                const float4* cr4 = (const float4*)(g_cnorm + (size_t)k * ED);
                float d = 0.f;
#pragma unroll
                for (int m = 0; m < 16; ++m) {
                    float4 u = cr4[m];
                    d = fmaf(za[4*m+0], u.x, d);
                    d = fmaf(za[4*m+1], u.y, d);
                    d = fmaf(za[4*m+2], u.z, d);
                    d = fmaf(za[4*m+3], u.w, d);
                }
                if (d > bv || (d == bv && k < bi)) { bv = d; bi = k; }
            }
            bvr[tid] = bv; bir[tid] = bi;
            __syncthreads();
            for (int s = 64; s > 0; s >>= 1) {
                if (tid < s) {
                    float v2 = bvr[tid + s]; int i2 = bir[tid + s];
                    if (v2 > bvr[tid] || (v2 == bvr[tid] && i2 < bir[tid])) {
                        bvr[tid] = v2; bir[tid] = i2;
                    }
                }
                __syncthreads();
            }
            if (tid == 0) idxs[tk] = bir[0];
            __syncthreads();
        }
    }
    __syncthreads();

    // ---------------- fused epilogue: gather/STE/loss/idx/bin ----------------
    // raw z re-read from global (coalesced, L2-hot; identical values to staged copy)
    int myidx = idxs[lane];
    const float4* er = (const float4*)(ew + (size_t)myidx * ED + warp * 16);
    float4 e0 = er[0], e1 = er[1], e2 = er[2], e3 = er[3];
    float vals[16] = {e0.x, e0.y, e0.z, e0.w, e1.x, e1.y, e1.z, e1.w,
                      e2.x, e2.y, e2.z, e2.w, e3.x, e3.y, e3.z, e3.w};
    float ssq = 0.f;
#pragma unroll
    for (int j = 0; j < 16; ++j) {
        int ch = warp * 16 + j;
        float zc = zb[(size_t)ch * CH_STRIDE + lane];
        float d  = vals[j] - zc;
        out_zq[(size_t)(b * 64 + ch) * 4096 + p0 + lane] = zc + d;
        ssq = fmaf(d, d, ssq);
    }
    red[tid] = ssq;
    __syncthreads();
    for (int s = 64; s > 0; s >>= 1) {
        if (tid < s) red[tid] += red[tid + s];
        __syncthreads();
    }
    if (tid == 0) g_partial[blockIdx.x] = red[0];

    if (tid < MCTA) {
        out_idx[tok0 + tid] = (float)idxs[tid];
        atomicAdd(&out_bin[idxs[tid]], 1.0f);
    }
}

// ---------------- loss finalize ----------------
__global__ void k4_loss(float* __restrict__ out_loss) {
    int lane = threadIdx.x;
    float s = 0.f;
    for (int i = lane * 32; i < lane * 32 + 32; ++i) s += g_partial[i];
#pragma unroll
    for (int off = 16; off > 0; off >>= 1)
        s += __shfl_xor_sync(0xffffffffu, s, off);
    if (lane == 0) {
        float m = s / 2097152.0f;
        out_loss[0] = 0.25f * m + m;
    }
}

extern "C" void kernel_launch(void* const* d_in, const int* in_sizes, int n_in,
                              void* d_out, int out_size) {
    const float* z  = (const float*)d_in[0];
    const float* ew = (const float*)d_in[1];
    float* out      = (float*)d_out;

    float* out_zq   = out;
    float* out_loss = out + OFF_LOSS;
    float* out_idx  = out + OFF_IDX;
    float* out_bin  = out + OFF_BIN;

    k_prep_c<<<NUM_EMBED / 128, 128>>>(ew, out_bin);

    cudaFuncSetAttribute(k_main, cudaFuncAttributeMaxDynamicSharedMemorySize, SM_TOT);
    k_main<<<NBLK, 128, SM_TOT>>>(z, ew, out_zq, out_idx, out_bin);

    k4_loss<<<1, 32>>>(out_loss);
}